// round 4
// baseline (speedup 1.0000x reference)
#include <cuda_runtime.h>
#include <math.h>

// Problem constants
#define NTOK  43520        // B * LQ
#define LQ_   21760
#define C_    256
#define NHEAD_ 8
#define DK_   32
#define FF_   1024
#define NL_   6

// Scratch (static device allocations; no cudaMalloc anywhere)
__device__ float g_x   [NTOK * C_];
__device__ float g_xp  [NTOK * C_];
__device__ float g_v   [NTOK * C_];
__device__ float g_off [NTOK * 256];   // NHEAD*NS*K*2 = 256
__device__ float g_att [NTOK * 128];   // NHEAD*NS*K   = 128
__device__ float g_aout[NTOK * C_];
__device__ float g_tmp [NTOK * C_];
__device__ float g_h   [NTOK * FF_];

// ---------------------------------------------------------------------------
// Elementwise add (float4)
// ---------------------------------------------------------------------------
__global__ void add_kernel(float* __restrict__ out, const float* __restrict__ a,
                           const float* __restrict__ b, int n4) {
    int i = blockIdx.x * blockDim.x + threadIdx.x;
    if (i < n4) {
        float4 av = reinterpret_cast<const float4*>(a)[i];
        float4 bv = reinterpret_cast<const float4*>(b)[i];
        float4 o;
        o.x = av.x + bv.x; o.y = av.y + bv.y;
        o.z = av.z + bv.z; o.w = av.w + bv.w;
        reinterpret_cast<float4*>(out)[i] = o;
    }
}

// ---------------------------------------------------------------------------
// SGEMM: C[M,N] = A[M,K] @ B[K,N] + bias[N], optional ReLU.
// 64x64 block tile, BK=16, 256 threads, 4x4 per-thread tile.
// Assumes M%64==0, N%64==0, K%16==0 (true for all shapes here).
// ---------------------------------------------------------------------------
template <bool RELU>
__global__ __launch_bounds__(256) void sgemm(const float* __restrict__ A,
                                             const float* __restrict__ B,
                                             const float* __restrict__ bias,
                                             float* __restrict__ C,
                                             int M, int K, int N) {
    __shared__ float As[16][65];   // [k][m], +1 pad -> conflict-free stores
    __shared__ float Bs[16][64];   // [k][n]

    const int tid = threadIdx.x;
    const int tx  = tid & 15;      // col group
    const int ty  = tid >> 4;      // row group

    const float* Ab = A + (size_t)blockIdx.y * 64 * K;
    const float* Bb = B + blockIdx.x * 64;

    const int arow = tid >> 2;          // 0..63
    const int acol = (tid & 3) * 4;     // 0,4,8,12
    const int brow = tid >> 4;          // 0..15
    const int bcol = (tid & 15) * 4;    // 0..60

    float acc[4][4];
    #pragma unroll
    for (int i = 0; i < 4; i++)
        #pragma unroll
        for (int j = 0; j < 4; j++) acc[i][j] = 0.f;

    for (int k0 = 0; k0 < K; k0 += 16) {
        float4 a4 = *reinterpret_cast<const float4*>(Ab + (size_t)arow * K + k0 + acol);
        As[acol + 0][arow] = a4.x;
        As[acol + 1][arow] = a4.y;
        As[acol + 2][arow] = a4.z;
        As[acol + 3][arow] = a4.w;
        *reinterpret_cast<float4*>(&Bs[brow][bcol]) =
            *reinterpret_cast<const float4*>(Bb + (size_t)(k0 + brow) * N + bcol);
        __syncthreads();

        #pragma unroll
        for (int kk = 0; kk < 16; kk++) {
            float ra[4];
            #pragma unroll
            for (int i = 0; i < 4; i++) ra[i] = As[kk][ty * 4 + i];
            float4 rb = *reinterpret_cast<const float4*>(&Bs[kk][tx * 4]);
            #pragma unroll
            for (int i = 0; i < 4; i++) {
                acc[i][0] += ra[i] * rb.x;
                acc[i][1] += ra[i] * rb.y;
                acc[i][2] += ra[i] * rb.z;
                acc[i][3] += ra[i] * rb.w;
            }
        }
        __syncthreads();
    }

    const int row0 = blockIdx.y * 64 + ty * 4;
    const int col0 = blockIdx.x * 64 + tx * 4;
    float4 bb = *reinterpret_cast<const float4*>(bias + col0);
    #pragma unroll
    for (int i = 0; i < 4; i++) {
        float4 o;
        o.x = acc[i][0] + bb.x;
        o.y = acc[i][1] + bb.y;
        o.z = acc[i][2] + bb.z;
        o.w = acc[i][3] + bb.w;
        if (RELU) {
            o.x = fmaxf(o.x, 0.f); o.y = fmaxf(o.y, 0.f);
            o.z = fmaxf(o.z, 0.f); o.w = fmaxf(o.w, 0.f);
        }
        *reinterpret_cast<float4*>(C + (size_t)(row0 + i) * N + col0) = o;
    }
}

// ---------------------------------------------------------------------------
// Softmax over groups of 16 (one thread per (token, head))
// ---------------------------------------------------------------------------
__global__ void softmax16(float* __restrict__ p, int n) {
    int i = blockIdx.x * blockDim.x + threadIdx.x;
    if (i >= n) return;
    float* q = p + (size_t)i * 16;
    float v[16];
    float m = -1e30f;
    #pragma unroll
    for (int j = 0; j < 16; j++) { v[j] = q[j]; m = fmaxf(m, v[j]); }
    float s = 0.f;
    #pragma unroll
    for (int j = 0; j < 16; j++) { v[j] = expf(v[j] - m); s += v[j]; }
    float inv = 1.f / s;
    #pragma unroll
    for (int j = 0; j < 16; j++) q[j] = v[j] * inv;
}

// ---------------------------------------------------------------------------
// Deformable attention sampling: one warp per (token, head); lane = channel.
// v layout: (B, LQ, C) with C = head*32 + d. Gathers are coalesced across lanes.
// ---------------------------------------------------------------------------
__global__ void deform_sample(const float* __restrict__ v,
                              const float* __restrict__ off,
                              const float* __restrict__ att,
                              const float* __restrict__ ref,
                              float* __restrict__ out) {
    int w = blockIdx.x * 8 + (threadIdx.x >> 5);
    if (w >= NTOK * NHEAD_) return;
    int lane = threadIdx.x & 31;
    int h = w & 7;
    int t = w >> 3;                 // token index = b*LQ + q
    int b = t / LQ_;

    float rx = ref[t * 2 + 0];
    float ry = ref[t * 2 + 1];
    const float* op = off + (size_t)t * 256 + h * 32;
    const float* ap = att + (size_t)t * 128 + h * 16;

    const int   Ws[4]     = {128, 64, 32, 16};
    const int   starts[4] = {0, 16384, 20480, 21504};

    float acc = 0.f;
    #pragma unroll
    for (int l = 0; l < 4; l++) {
        const int   W    = Ws[l];
        const float invW = 1.f / (float)W;
        const float Wm1  = (float)(W - 1);
        const float* vb  = v + ((size_t)(b * LQ_ + starts[l])) * 256 + h * 32 + lane;
        #pragma unroll
        for (int k = 0; k < 4; k++) {
            float ox  = op[l * 8 + k * 2 + 0];
            float oy  = op[l * 8 + k * 2 + 1];
            float wgt = ap[l * 4 + k];
            float x = (rx + ox * invW) * Wm1;
            float y = (ry + oy * invW) * Wm1;
            x = fminf(fmaxf(x, 0.f), Wm1);
            y = fminf(fmaxf(y, 0.f), Wm1);
            float x0f = floorf(x), y0f = floorf(y);
            float wx = x - x0f, wy = y - y0f;
            int x0 = (int)x0f, y0 = (int)y0f;
            int x1 = min(x0 + 1, W - 1);
            int y1 = min(y0 + 1, W - 1);
            const float* r0 = vb + (size_t)(y0 * W) * 256;
            const float* r1 = vb + (size_t)(y1 * W) * 256;
            float v00 = r0[x0 * 256], v10 = r0[x1 * 256];
            float v01 = r1[x0 * 256], v11 = r1[x1 * 256];
            float top = v00 + wx * (v10 - v00);
            float bot = v01 + wx * (v11 - v01);
            acc += wgt * (top + wy * (bot - top));
        }
    }
    out[(size_t)t * 256 + h * 32 + lane] = acc;
}

// ---------------------------------------------------------------------------
// LayerNorm( a + b ) over C=256, one warp per row (8 channels/lane)
// ---------------------------------------------------------------------------
__global__ void ln_kernel(float* __restrict__ out, const float* __restrict__ a,
                          const float* __restrict__ b, const float* __restrict__ gm,
                          const float* __restrict__ bt) {
    int row = blockIdx.x * 8 + (threadIdx.x >> 5);
    if (row >= NTOK) return;
    int lane = threadIdx.x & 31;
    const float* ap = a + (size_t)row * 256;
    const float* bp = b + (size_t)row * 256;

    float vals[8];
    float s = 0.f;
    #pragma unroll
    for (int i = 0; i < 8; i++) {
        vals[i] = ap[lane + i * 32] + bp[lane + i * 32];
        s += vals[i];
    }
    #pragma unroll
    for (int o = 16; o; o >>= 1) s += __shfl_xor_sync(0xffffffffu, s, o);
    float mean = s * (1.f / 256.f);

    float var = 0.f;
    #pragma unroll
    for (int i = 0; i < 8; i++) {
        float d = vals[i] - mean;
        var += d * d;
    }
    #pragma unroll
    for (int o = 16; o; o >>= 1) var += __shfl_xor_sync(0xffffffffu, var, o);
    float rstd = rsqrtf(var * (1.f / 256.f) + 1e-5f);

    #pragma unroll
    for (int i = 0; i < 8; i++) {
        int c = lane + i * 32;
        out[(size_t)row * 256 + c] = (vals[i] - mean) * rstd * gm[c] + bt[c];
    }
}

// ---------------------------------------------------------------------------
// Launch: 6 encoder layers
// ---------------------------------------------------------------------------
extern "C" void kernel_launch(void* const* d_in, const int* in_sizes, int n_in,
                              void* d_out, int out_size) {
    const float* src  = (const float*)d_in[0];
    const float* pos  = (const float*)d_in[1];
    const float* ref  = (const float*)d_in[2];
    const float* Woff = (const float*)d_in[3];
    const float* boff = (const float*)d_in[4];
    const float* Wat  = (const float*)d_in[5];
    const float* bat  = (const float*)d_in[6];
    const float* Wv   = (const float*)d_in[7];
    const float* bv   = (const float*)d_in[8];
    const float* Wo   = (const float*)d_in[9];
    const float* bo   = (const float*)d_in[10];
    const float* W1   = (const float*)d_in[11];
    const float* b1   = (const float*)d_in[12];
    const float* W2   = (const float*)d_in[13];
    const float* b2   = (const float*)d_in[14];
    const float* n1s  = (const float*)d_in[15];
    const float* n1b  = (const float*)d_in[16];
    const float* n2s  = (const float*)d_in[17];
    const float* n2b  = (const float*)d_in[18];

    float *x, *xp, *v, *off, *att, *aout, *tmp, *hbuf;
    cudaGetSymbolAddress((void**)&x,    g_x);
    cudaGetSymbolAddress((void**)&xp,   g_xp);
    cudaGetSymbolAddress((void**)&v,    g_v);
    cudaGetSymbolAddress((void**)&off,  g_off);
    cudaGetSymbolAddress((void**)&att,  g_att);
    cudaGetSymbolAddress((void**)&aout, g_aout);
    cudaGetSymbolAddress((void**)&tmp,  g_tmp);
    cudaGetSymbolAddress((void**)&hbuf, g_h);

    const int n4 = NTOK * C_ / 4;
    dim3 g256 (256  / 64, NTOK / 64);   // (4, 680)
    dim3 g128 (128  / 64, NTOK / 64);   // (2, 680)
    dim3 g1024(1024 / 64, NTOK / 64);   // (16, 680)

    for (int i = 0; i < NL_; i++) {
        // xp = x + pos  (x = src on first layer)
        add_kernel<<<(n4 + 255) / 256, 256>>>(xp, (i == 0) ? src : x, pos, n4);

        // value / offset / attention-logit projections
        sgemm<false><<<g256, 256>>>(xp, Wv  + (size_t)i * 256 * 256, bv  + i * 256, v,   NTOK, 256, 256);
        sgemm<false><<<g256, 256>>>(xp, Woff + (size_t)i * 256 * 256, boff + i * 256, off, NTOK, 256, 256);
        sgemm<false><<<g128, 256>>>(xp, Wat + (size_t)i * 256 * 128, bat + i * 128, att, NTOK, 256, 128);

        // softmax over NS*K=16 per (token, head)
        softmax16<<<(NTOK * NHEAD_ + 255) / 256, 256>>>(att, NTOK * NHEAD_);

        // deformable sampling: 8 warps per block, one warp per (token, head)
        deform_sample<<<NTOK, 256>>>(v, off, att, ref, aout);

        // output projection + residual + LN1
        sgemm<false><<<g256, 256>>>(aout, Wo + (size_t)i * 256 * 256, bo + i * 256, tmp, NTOK, 256, 256);
        ln_kernel<<<NTOK / 8, 256>>>(x, xp, tmp, n1s + i * 256, n1b + i * 256);

        // FFN + residual + LN2
        sgemm<true ><<<g1024, 256>>>(x,    W1 + (size_t)i * 256 * 1024, b1 + i * 1024, hbuf, NTOK, 256, 1024);
        sgemm<false><<<g256,  256>>>(hbuf, W2 + (size_t)i * 1024 * 256, b2 + i * 256,  tmp,  NTOK, 1024, 256);
        ln_kernel<<<NTOK / 8, 256>>>((i == NL_ - 1) ? (float*)d_out : x,
                                     x, tmp, n2s + i * 256, n2b + i * 256);
    }
}

// round 6
// speedup vs baseline: 2.0832x; 2.0832x over previous
#include <cuda_runtime.h>
#include <cuda_bf16.h>
#include <math.h>
#include <stdint.h>

// Problem constants
#define NTOK  43520        // B * LQ
#define LQ_   21760
#define C_    256
#define NHEAD_ 8
#define FF_   1024
#define NL_   6

// ---------------------------------------------------------------------------
// Scratch (static device allocations; no cudaMalloc anywhere)
// ---------------------------------------------------------------------------
__device__ float g_x   [NTOK * C_];
__device__ float g_xp  [NTOK * C_];
__device__ float g_v   [NTOK * C_];
__device__ float g_off [NTOK * 256];
__device__ float g_att [NTOK * 128];
__device__ float g_aout[NTOK * C_];
__device__ float g_tmp [NTOK * C_];
__device__ float g_h   [NTOK * FF_];
// transposed+split weights for the current GEMM: [N,K] bf16, max 1024*256
__device__ __align__(16) __nv_bfloat16 g_wh[1024 * 256];
__device__ __align__(16) __nv_bfloat16 g_wl[1024 * 256];

// ---------------------------------------------------------------------------
// PTX helpers (sm_103 base target: mma.sync / ldmatrix / cp.async only)
// ---------------------------------------------------------------------------
__device__ __forceinline__ uint32_t smem_u32(const void* p) {
    return (uint32_t)__cvta_generic_to_shared(p);
}
__device__ __forceinline__ void cp_async16(uint32_t saddr, const void* gaddr) {
    asm volatile("cp.async.cg.shared.global [%0], [%1], 16;" :: "r"(saddr), "l"(gaddr));
}
__device__ __forceinline__ void cp_commit() {
    asm volatile("cp.async.commit_group;" ::: "memory");
}
__device__ __forceinline__ void cp_wait0() {
    asm volatile("cp.async.wait_group 0;" ::: "memory");
}
__device__ __forceinline__ void ldsm4(uint32_t* r, uint32_t a) {
    asm volatile("ldmatrix.sync.aligned.m8n8.x4.shared.b16 {%0,%1,%2,%3}, [%4];"
                 : "=r"(r[0]), "=r"(r[1]), "=r"(r[2]), "=r"(r[3]) : "r"(a));
}
__device__ __forceinline__ void ldsm2(uint32_t* r, uint32_t a) {
    asm volatile("ldmatrix.sync.aligned.m8n8.x2.shared.b16 {%0,%1}, [%2];"
                 : "=r"(r[0]), "=r"(r[1]) : "r"(a));
}
__device__ __forceinline__ void mma16816(float* c, const uint32_t* a, const uint32_t* b) {
    asm volatile("mma.sync.aligned.m16n8k16.row.col.f32.bf16.bf16.f32 "
                 "{%0,%1,%2,%3}, {%4,%5,%6,%7}, {%8,%9}, {%0,%1,%2,%3};"
                 : "+f"(c[0]), "+f"(c[1]), "+f"(c[2]), "+f"(c[3])
                 : "r"(a[0]), "r"(a[1]), "r"(a[2]), "r"(a[3]), "r"(b[0]), "r"(b[1]));
}

// ---------------------------------------------------------------------------
// Weight prep: W fp32 [K,N] -> Bt_hi/Bt_lo bf16 [N,K]  (transpose + hi/lo split)
// grid (N/32, K/32), block (32,8)
// ---------------------------------------------------------------------------
__global__ void prep_w(const float* __restrict__ W, __nv_bfloat16* __restrict__ Bh,
                       __nv_bfloat16* __restrict__ Bl, int K, int N) {
    __shared__ float t[32][33];
    int k0 = blockIdx.y * 32, n0 = blockIdx.x * 32;
    for (int i = threadIdx.y; i < 32; i += 8)
        t[i][threadIdx.x] = W[(size_t)(k0 + i) * N + n0 + threadIdx.x];
    __syncthreads();
    for (int i = threadIdx.y; i < 32; i += 8) {
        float x = t[threadIdx.x][i];                 // W[k0+tx][n0+i]
        __nv_bfloat16 h = __float2bfloat16(x);
        float lo = x - __bfloat162float(h);
        size_t o = (size_t)(n0 + i) * K + k0 + threadIdx.x;
        Bh[o] = h;
        Bl[o] = __float2bfloat16(lo);
    }
}

// ---------------------------------------------------------------------------
// Split-bf16 HMMA GEMM: C[M,N] = A[M,K](fp32) @ Bt[N,K](bf16 hi/lo)^T + bias
// 3 products in fp32 accumulators: Ahi*Bhi + Ahi*Blo + Alo*Bhi.
// Tile 128x128, BK=32, 256 threads (8 warps, 2x4; warp tile 64x32).
// Smem rows padded to 40 bf16 (80B) -> conflict-free ldmatrix, 16B-aligned rows.
// Double-buffered; cp.async for B, register-prefetched A (fp32->hi/lo split).
// M%128==0, N%128==0, K%32==0.
// ---------------------------------------------------------------------------
#define OFF_AH 0
#define OFF_AL 10240
#define OFF_BH 20480
#define OFF_BL 30720
#define STAGE_BYTES 40960

template <bool RELU>
__global__ __launch_bounds__(256) void gemm_mma(const float* __restrict__ A,
                                                const __nv_bfloat16* __restrict__ Bh,
                                                const __nv_bfloat16* __restrict__ Bl,
                                                const float* __restrict__ bias,
                                                float* __restrict__ C,
                                                int M, int K, int N_) {
    extern __shared__ char smem[];
    const uint32_t sbase = smem_u32(smem);
    const int tid  = threadIdx.x;
    const int wid  = tid >> 5;
    const int lane = tid & 31;
    const int warpM = wid >> 2;          // 0..1  -> M offset *64
    const int warpN = wid & 3;           // 0..3  -> N offset *32
    const int m0 = blockIdx.y * 128;
    const int n0 = blockIdx.x * 128;

    float acc[4][4][4];
    #pragma unroll
    for (int i = 0; i < 4; i++)
        #pragma unroll
        for (int j = 0; j < 4; j++)
            #pragma unroll
            for (int r = 0; r < 4; r++) acc[i][j][r] = 0.f;

    const int nkt = K >> 5;
    float4 apre[4];

    // ---- helpers as lambdas ----
    auto loadA = [&](int kt) {
        #pragma unroll
        for (int i = 0; i < 4; i++) {
            int idx = tid + i * 256;
            int row = idx >> 3;
            int c4  = (idx & 7) << 2;
            apre[i] = *reinterpret_cast<const float4*>(A + (size_t)(m0 + row) * K + kt * 32 + c4);
        }
    };
    auto storeA = [&](char* stage) {
        #pragma unroll
        for (int i = 0; i < 4; i++) {
            int idx = tid + i * 256;
            int row = idx >> 3;
            int c4  = (idx & 7) << 2;
            float4 a4 = apre[i];
            __nv_bfloat162 h01 = __floats2bfloat162_rn(a4.x, a4.y);
            __nv_bfloat162 h23 = __floats2bfloat162_rn(a4.z, a4.w);
            __nv_bfloat162 l01 = __floats2bfloat162_rn(a4.x - __bfloat162float(h01.x),
                                                       a4.y - __bfloat162float(h01.y));
            __nv_bfloat162 l23 = __floats2bfloat162_rn(a4.z - __bfloat162float(h23.x),
                                                       a4.w - __bfloat162float(h23.y));
            int off = row * 80 + c4 * 2;
            *reinterpret_cast<uint2*>(stage + OFF_AH + off) =
                make_uint2(*reinterpret_cast<uint32_t*>(&h01), *reinterpret_cast<uint32_t*>(&h23));
            *reinterpret_cast<uint2*>(stage + OFF_AL + off) =
                make_uint2(*reinterpret_cast<uint32_t*>(&l01), *reinterpret_cast<uint32_t*>(&l23));
        }
    };
    auto loadB = [&](int kt, uint32_t stage_u) {
        #pragma unroll
        for (int i = 0; i < 2; i++) {
            int idx = tid + i * 256;              // 0..511
            int n = idx >> 2;
            int c = idx & 3;
            size_t g = (size_t)(n0 + n) * K + kt * 32 + c * 8;
            uint32_t s = stage_u + n * 80 + c * 16;
            cp_async16(s + OFF_BH, Bh + g);
            cp_async16(s + OFF_BL, Bl + g);
        }
    };
    auto compute = [&](uint32_t stage_u) {
        const int ar = lane & 15;
        const int ak = (lane >> 4) * 8;
        const int bn = lane & 7;
        const int bk = ((lane >> 3) & 1) * 8;
        #pragma unroll
        for (int kk = 0; kk < 32; kk += 16) {
            uint32_t ah[4][4], al[4][4], bh[4][2], bl[4][2];
            #pragma unroll
            for (int i = 0; i < 4; i++) {
                uint32_t a = stage_u + ((warpM * 64 + i * 16 + ar) * 40 + kk + ak) * 2;
                ldsm4(ah[i], a + OFF_AH);
                ldsm4(al[i], a + OFF_AL);
            }
            #pragma unroll
            for (int j = 0; j < 4; j++) {
                uint32_t b = stage_u + ((warpN * 32 + j * 8 + bn) * 40 + kk + bk) * 2;
                ldsm2(bh[j], b + OFF_BH);
                ldsm2(bl[j], b + OFF_BL);
            }
            #pragma unroll
            for (int i = 0; i < 4; i++)
                #pragma unroll
                for (int j = 0; j < 4; j++) {
                    mma16816(acc[i][j], ah[i], bh[j]);
                    mma16816(acc[i][j], ah[i], bl[j]);
                    mma16816(acc[i][j], al[i], bh[j]);
                }
        }
    };

    // ---- prologue ----
    loadA(0);
    loadB(0, sbase);
    cp_commit();
    storeA(smem);
    cp_wait0();
    __syncthreads();

    // ---- main loop (double buffered) ----
    for (int kt = 0; kt < nkt; kt++) {
        const uint32_t cur = sbase + (uint32_t)(kt & 1) * STAGE_BYTES;
        char* nstage = smem + ((kt + 1) & 1) * STAGE_BYTES;
        const uint32_t nxt = sbase + (uint32_t)((kt + 1) & 1) * STAGE_BYTES;
        if (kt + 1 < nkt) {
            loadA(kt + 1);
            loadB(kt + 1, nxt);
            cp_commit();
        }
        compute(cur);
        if (kt + 1 < nkt) {
            storeA(nstage);
            cp_wait0();
        }
        __syncthreads();
    }

    // ---- epilogue: bias (+ReLU), fp32 stores ----
    const int tr = lane >> 2;
    const int tc = (lane & 3) * 2;
    #pragma unroll
    for (int i = 0; i < 4; i++) {
        #pragma unroll
        for (int j = 0; j < 4; j++) {
            int row = m0 + warpM * 64 + i * 16 + tr;
            int col = n0 + warpN * 32 + j * 8 + tc;
            float2 bb = *reinterpret_cast<const float2*>(bias + col);
            float2 o0, o1;
            o0.x = acc[i][j][0] + bb.x; o0.y = acc[i][j][1] + bb.y;
            o1.x = acc[i][j][2] + bb.x; o1.y = acc[i][j][3] + bb.y;
            if (RELU) {
                o0.x = fmaxf(o0.x, 0.f); o0.y = fmaxf(o0.y, 0.f);
                o1.x = fmaxf(o1.x, 0.f); o1.y = fmaxf(o1.y, 0.f);
            }
            *reinterpret_cast<float2*>(C + (size_t)row * N_ + col) = o0;
            *reinterpret_cast<float2*>(C + (size_t)(row + 8) * N_ + col) = o1;
        }
    }
}

// ---------------------------------------------------------------------------
// Elementwise add (float4)
// ---------------------------------------------------------------------------
__global__ void add_kernel(float* __restrict__ out, const float* __restrict__ a,
                           const float* __restrict__ b, int n4) {
    int i = blockIdx.x * blockDim.x + threadIdx.x;
    if (i < n4) {
        float4 av = reinterpret_cast<const float4*>(a)[i];
        float4 bv = reinterpret_cast<const float4*>(b)[i];
        float4 o;
        o.x = av.x + bv.x; o.y = av.y + bv.y;
        o.z = av.z + bv.z; o.w = av.w + bv.w;
        reinterpret_cast<float4*>(out)[i] = o;
    }
}

// ---------------------------------------------------------------------------
// Softmax over groups of 16 (one thread per (token, head))
// ---------------------------------------------------------------------------
__global__ void softmax16(float* __restrict__ p, int n) {
    int i = blockIdx.x * blockDim.x + threadIdx.x;
    if (i >= n) return;
    float* q = p + (size_t)i * 16;
    float v[16];
    float m = -1e30f;
    #pragma unroll
    for (int j = 0; j < 16; j++) { v[j] = q[j]; m = fmaxf(m, v[j]); }
    float s = 0.f;
    #pragma unroll
    for (int j = 0; j < 16; j++) { v[j] = expf(v[j] - m); s += v[j]; }
    float inv = 1.f / s;
    #pragma unroll
    for (int j = 0; j < 16; j++) q[j] = v[j] * inv;
}

// ---------------------------------------------------------------------------
// Deformable attention sampling (one warp per (token, head); lane = channel)
// ---------------------------------------------------------------------------
__global__ void deform_sample(const float* __restrict__ v,
                              const float* __restrict__ off,
                              const float* __restrict__ att,
                              const float* __restrict__ ref,
                              float* __restrict__ out) {
    int w = blockIdx.x * 8 + (threadIdx.x >> 5);
    if (w >= NTOK * NHEAD_) return;
    int lane = threadIdx.x & 31;
    int h = w & 7;
    int t = w >> 3;
    int b = t / LQ_;

    float rx = ref[t * 2 + 0];
    float ry = ref[t * 2 + 1];
    const float* op = off + (size_t)t * 256 + h * 32;
    const float* ap = att + (size_t)t * 128 + h * 16;

    const int Ws[4]     = {128, 64, 32, 16};
    const int starts[4] = {0, 16384, 20480, 21504};

    float acc = 0.f;
    #pragma unroll
    for (int l = 0; l < 4; l++) {
        const int   W    = Ws[l];
        const float invW = 1.f / (float)W;
        const float Wm1  = (float)(W - 1);
        const float* vb  = v + ((size_t)(b * LQ_ + starts[l])) * 256 + h * 32 + lane;
        #pragma unroll
        for (int k = 0; k < 4; k++) {
            float ox  = op[l * 8 + k * 2 + 0];
            float oy  = op[l * 8 + k * 2 + 1];
            float wgt = ap[l * 4 + k];
            float x = (rx + ox * invW) * Wm1;
            float y = (ry + oy * invW) * Wm1;
            x = fminf(fmaxf(x, 0.f), Wm1);
            y = fminf(fmaxf(y, 0.f), Wm1);
            float x0f = floorf(x), y0f = floorf(y);
            float wx = x - x0f, wy = y - y0f;
            int x0 = (int)x0f, y0 = (int)y0f;
            int x1 = min(x0 + 1, W - 1);
            int y1 = min(y0 + 1, W - 1);
            const float* r0 = vb + (size_t)(y0 * W) * 256;
            const float* r1 = vb + (size_t)(y1 * W) * 256;
            float v00 = r0[x0 * 256], v10 = r0[x1 * 256];
            float v01 = r1[x0 * 256], v11 = r1[x1 * 256];
            float top = v00 + wx * (v10 - v00);
            float bot = v01 + wx * (v11 - v01);
            acc += wgt * (top + wy * (bot - top));
        }
    }
    out[(size_t)t * 256 + h * 32 + lane] = acc;
}

// ---------------------------------------------------------------------------
// LayerNorm( a + b ) over C=256, one warp per row
// ---------------------------------------------------------------------------
__global__ void ln_kernel(float* __restrict__ out, const float* __restrict__ a,
                          const float* __restrict__ b, const float* __restrict__ gm,
                          const float* __restrict__ bt) {
    int row = blockIdx.x * 8 + (threadIdx.x >> 5);
    if (row >= NTOK) return;
    int lane = threadIdx.x & 31;
    const float* ap = a + (size_t)row * 256;
    const float* bp = b + (size_t)row * 256;

    float vals[8];
    float s = 0.f;
    #pragma unroll
    for (int i = 0; i < 8; i++) {
        vals[i] = ap[lane + i * 32] + bp[lane + i * 32];
        s += vals[i];
    }
    #pragma unroll
    for (int o = 16; o; o >>= 1) s += __shfl_xor_sync(0xffffffffu, s, o);
    float mean = s * (1.f / 256.f);

    float var = 0.f;
    #pragma unroll
    for (int i = 0; i < 8; i++) { float d = vals[i] - mean; var += d * d; }
    #pragma unroll
    for (int o = 16; o; o >>= 1) var += __shfl_xor_sync(0xffffffffu, var, o);
    float rstd = rsqrtf(var * (1.f / 256.f) + 1e-5f);

    #pragma unroll
    for (int i = 0; i < 8; i++) {
        int c = lane + i * 32;
        out[(size_t)row * 256 + c] = (vals[i] - mean) * rstd * gm[c] + bt[c];
    }
}

// ---------------------------------------------------------------------------
// Launch
// ---------------------------------------------------------------------------
static void tc_gemm(const float* A, const float* W, const float* bias, float* C,
                    int M, int K, int N, bool relu,
                    __nv_bfloat16* wh, __nv_bfloat16* wl) {
    prep_w<<<dim3(N / 32, K / 32), dim3(32, 8)>>>(W, wh, wl, K, N);
    dim3 grid(N / 128, M / 128);
    size_t shm = 2 * STAGE_BYTES;
    if (relu) gemm_mma<true ><<<grid, 256, shm>>>(A, wh, wl, bias, C, M, K, N);
    else      gemm_mma<false><<<grid, 256, shm>>>(A, wh, wl, bias, C, M, K, N);
}

extern "C" void kernel_launch(void* const* d_in, const int* in_sizes, int n_in,
                              void* d_out, int out_size) {
    const float* src  = (const float*)d_in[0];
    const float* pos  = (const float*)d_in[1];
    const float* ref  = (const float*)d_in[2];
    const float* Woff = (const float*)d_in[3];
    const float* boff = (const float*)d_in[4];
    const float* Wat  = (const float*)d_in[5];
    const float* bat  = (const float*)d_in[6];
    const float* Wv   = (const float*)d_in[7];
    const float* bv   = (const float*)d_in[8];
    const float* Wo   = (const float*)d_in[9];
    const float* bo   = (const float*)d_in[10];
    const float* W1   = (const float*)d_in[11];
    const float* b1   = (const float*)d_in[12];
    const float* W2   = (const float*)d_in[13];
    const float* b2   = (const float*)d_in[14];
    const float* n1s  = (const float*)d_in[15];
    const float* n1b  = (const float*)d_in[16];
    const float* n2s  = (const float*)d_in[17];
    const float* n2b  = (const float*)d_in[18];

    float *x, *xp, *v, *off, *att, *aout, *tmp, *hbuf;
    __nv_bfloat16 *wh, *wl;
    cudaGetSymbolAddress((void**)&x,    g_x);
    cudaGetSymbolAddress((void**)&xp,   g_xp);
    cudaGetSymbolAddress((void**)&v,    g_v);
    cudaGetSymbolAddress((void**)&off,  g_off);
    cudaGetSymbolAddress((void**)&att,  g_att);
    cudaGetSymbolAddress((void**)&aout, g_aout);
    cudaGetSymbolAddress((void**)&tmp,  g_tmp);
    cudaGetSymbolAddress((void**)&hbuf, g_h);
    cudaGetSymbolAddress((void**)&wh,   g_wh);
    cudaGetSymbolAddress((void**)&wl,   g_wl);

    size_t shm = 2 * STAGE_BYTES;
    cudaFuncSetAttribute(gemm_mma<false>, cudaFuncAttributeMaxDynamicSharedMemorySize, (int)shm);
    cudaFuncSetAttribute(gemm_mma<true >, cudaFuncAttributeMaxDynamicSharedMemorySize, (int)shm);

    const int n4 = NTOK * C_ / 4;

    for (int i = 0; i < NL_; i++) {
        add_kernel<<<(n4 + 255) / 256, 256>>>(xp, (i == 0) ? src : x, pos, n4);

        tc_gemm(xp, Wv   + (size_t)i * 256 * 256,  bv   + i * 256,  v,   NTOK, 256, 256,  false, wh, wl);
        tc_gemm(xp, Woff + (size_t)i * 256 * 256,  boff + i * 256,  off, NTOK, 256, 256,  false, wh, wl);
        tc_gemm(xp, Wat  + (size_t)i * 256 * 128,  bat  + i * 128,  att, NTOK, 256, 128,  false, wh, wl);

        softmax16<<<(NTOK * NHEAD_ + 255) / 256, 256>>>(att, NTOK * NHEAD_);
        deform_sample<<<NTOK, 256>>>(v, off, att, ref, aout);

        tc_gemm(aout, Wo + (size_t)i * 256 * 256,  bo + i * 256,  tmp, NTOK, 256, 256, false, wh, wl);
        ln_kernel<<<NTOK / 8, 256>>>(x, xp, tmp, n1s + i * 256, n1b + i * 256);

        tc_gemm(x,    W1 + (size_t)i * 256 * 1024, b1 + i * 1024, hbuf, NTOK, 256, 1024, true,  wh, wl);
        tc_gemm(hbuf, W2 + (size_t)i * 1024 * 256, b2 + i * 256,  tmp,  NTOK, 1024, 256, false, wh, wl);
        ln_kernel<<<NTOK / 8, 256>>>((i == NL_ - 1) ? (float*)d_out : x,
                                     x, tmp, n2s + i * 256, n2b + i * 256);
    }
}